// round 14
// baseline (speedup 1.0000x reference)
#include <cuda_runtime.h>
#include <cuda_bf16.h>

// BERTLatticeEmbedding: ragged segment mean-pool.
// hidden [B,S,H] f32, word_ids [B,S] int32 (sorted per row),
// out [B,T,H] f32. B=64, S=512, H=768, T=400.
//
// R10: SINGLE fused kernel. Block = (b, 16-word tile), 512 threads:
//  - word_ids row (2KB) staged to SMEM in one coalesced pass (L2-hot:
//    25 blocks/sample share it), 17 LDS binary searches for boundaries.
//  - payload identical to R9: warp = (word-pair, half-row), 6-LDG bursts,
//    warp-uniform predicated A/B accumulation, __ldcs reads, write-back
//    stores (output parks in L2).
//  Removes the separate bounds kernel launch and halves prologue count.

#define B_DIM 64
#define S_DIM 512
#define H_DIM 768
#define T_DIM 400
#define H4    (H_DIM / 4)       // 192 float4 per row
#define HALF4 (H4 / 2)          // 96 float4 per half-row
#define TPB   512               // 16 warps
#define WORDS_PER_BLK 16
#define NTILES (T_DIM / WORDS_PER_BLK)   // 25

__device__ __forceinline__ void f4add(float4& a, const float4 v) {
    a.x += v.x; a.y += v.y; a.z += v.z; a.w += v.w;
}
__device__ __forceinline__ void f4scale(float4& a, const float s) {
    a.x *= s; a.y *= s; a.z *= s; a.w *= s;
}

__global__ __launch_bounds__(TPB, 2) void pool_kernel(
    const float* __restrict__ hidden,
    const int* __restrict__ word_ids,
    float* __restrict__ out)
{
    __shared__ int s_row[S_DIM];
    __shared__ int s_b[WORDS_PER_BLK + 1];   // start[wbase .. wbase+16]

    const int b     = blockIdx.y;
    const int wbase = blockIdx.x * WORDS_PER_BLK;
    const int tid   = threadIdx.x;
    const int warp  = tid >> 5;
    const int lane  = tid & 31;

    // Stage this sample's word_ids row: 512 threads, 1 int each (coalesced).
    s_row[tid] = __ldg(word_ids + b * S_DIM + tid);
    __syncthreads();

    // 17 boundaries via LDS binary search.
    if (tid <= WORDS_PER_BLK) {
        const int target = wbase + tid;
        int lo = 0, hi = S_DIM;
        while (lo < hi) {
            int mid = (lo + hi) >> 1;
            if (s_row[mid] < target) lo = mid + 1; else hi = mid;
        }
        s_b[tid] = lo;
    }
    __syncthreads();

    const int pair = warp >> 1;               // 0..7
    const int half = warp & 1;
    const int w0   = wbase + pair * 2;
    const int off  = half * HALF4 + lane;

    const int s0 = s_b[pair * 2];
    const int s1 = s_b[pair * 2 + 1];
    const int s2 = s_b[pair * 2 + 2];

    const float4* __restrict__ hin =
        reinterpret_cast<const float4*>(hidden + (size_t)b * S_DIM * H_DIM) + off;

    const float4 Z = make_float4(0.f, 0.f, 0.f, 0.f);
    float4 A0 = Z, A1 = Z, A2 = Z;   // word w0
    float4 B0 = Z, B1 = Z, B2 = Z;   // word w0+1

    // Combined contiguous piece range [s0, s2); warp-uniform predicates.
    for (int s = s0; s < s2; s += 2) {
        const float4* q = hin + (size_t)s * H4;
        const bool has1 = (s + 1 < s2);
        float4 v0 = __ldcs(q);
        float4 v1 = __ldcs(q + 32);
        float4 v2 = __ldcs(q + 64);
        float4 u0, u1, u2;
        if (has1) {
            u0 = __ldcs(q + H4);
            u1 = __ldcs(q + H4 + 32);
            u2 = __ldcs(q + H4 + 64);
        }
        if (s < s1) { f4add(A0, v0); f4add(A1, v1); f4add(A2, v2); }
        else        { f4add(B0, v0); f4add(B1, v1); f4add(B2, v2); }
        if (has1) {
            if (s + 1 < s1) { f4add(A0, u0); f4add(A1, u1); f4add(A2, u2); }
            else            { f4add(B0, u0); f4add(B1, u1); f4add(B2, u2); }
        }
    }

    const int c0 = s1 - s0;
    const int c1 = s2 - s1;
    const float invA = 1.0f / (float)(c0 > 0 ? c0 : 1);
    const float invB = 1.0f / (float)(c1 > 0 ? c1 : 1);
    f4scale(A0, invA); f4scale(A1, invA); f4scale(A2, invA);
    f4scale(B0, invB); f4scale(B1, invB); f4scale(B2, invB);

    // Write-back stores: output parks in L2, evicts after kernel.
    float4* __restrict__ opA =
        reinterpret_cast<float4*>(out + ((size_t)b * T_DIM + w0) * H_DIM) + off;
    float4* __restrict__ opB = opA + H4;
    opA[0]  = A0;
    opA[32] = A1;
    opA[64] = A2;
    opB[0]  = B0;
    opB[32] = B1;
    opB[64] = B2;
}

extern "C" void kernel_launch(void* const* d_in, const int* in_sizes, int n_in,
                              void* d_out, int out_size)
{
    const float* hidden   = (const float*)d_in[0];
    const int*   word_ids = (const int*)d_in[1];
    float* out = (float*)d_out;

    dim3 grid(NTILES, B_DIM);          // 25 x 64 = 1600 blocks
    pool_kernel<<<grid, TPB>>>(hidden, word_ids, out);
}